// round 1
// baseline (speedup 1.0000x reference)
#include <cuda_runtime.h>
#include <cuda_bf16.h>

#define V_N 50000
#define E_N 800000
#define HEADS 4
#define FOUT 32
#define NHF 128     // HEADS*FOUT
#define NODE_IN 128
#define EDGE_IN 16

// ---------------- scratch (device globals; no allocation allowed) ----------
__device__ float g_ft[(size_t)V_N * NHF];     // projected node feats  [V,128]
__device__ float g_el[V_N * HEADS];           // left attention logits [V,4]
__device__ float g_er[V_N * HEADS];           // right attention logits[V,4]
__device__ float g_ex[(size_t)E_N * HEADS];   // exp(logit) per edge   [E,4]
__device__ float g_esum[V_N * HEADS];         // softmax denominators  [V,4]
__device__ float g_Me[EDGE_IN * HEADS];       // folded edge->logit matrix [16,4]

// ---------------- kernel 0: fold W_edge*attn_e, zero esum ------------------
__global__ void init_kernel(const float* __restrict__ W_edge,
                            const float* __restrict__ attn_e) {
    int tid = blockIdx.x * blockDim.x + threadIdx.x;
    for (int i = tid; i < V_N * HEADS; i += gridDim.x * blockDim.x)
        g_esum[i] = 0.f;
    if (blockIdx.x == 0 && threadIdx.x < EDGE_IN * HEADS) {
        int i = threadIdx.x / HEADS;   // 0..15 edge-input index
        int h = threadIdx.x % HEADS;   // head
        float s = 0.f;
        #pragma unroll
        for (int f = 0; f < FOUT; f++)
            s += W_edge[i * NHF + h * FOUT + f] * attn_e[h * FOUT + f];
        g_Me[threadIdx.x] = s;         // layout Me[i*4+h]
    }
}

// ---------------- kernel 1: SGEMM  C[M,128] = A[M,128] @ B[128,128] --------
#define BM 128
#define BN 128
#define BK 16
#define TM 8
#define TN 8
// 256 threads

__global__ void __launch_bounds__(256)
sgemm128(const float* __restrict__ A, const float* __restrict__ B,
         int M, const float* __restrict__ bias, int write_ft,
         float* __restrict__ outC) {
    const int K = 128, N = 128;
    __shared__ float As[BK][BM];
    __shared__ float Bs[BK][BN];
    float* C = write_ft ? g_ft : outC;

    int tid = threadIdx.x;
    int blockRow = blockIdx.x * BM;
    int tx = tid % 16, ty = tid / 16;

    int aRow = tid / 4;           // 0..63 (two passes)
    int aCol = (tid % 4) * 4;     // 0,4,8,12
    int bRow = tid / 32;          // 0..7 (two passes)
    int bCol = (tid % 32) * 4;

    float acc[TM][TN];
    #pragma unroll
    for (int i = 0; i < TM; i++)
        #pragma unroll
        for (int j = 0; j < TN; j++) acc[i][j] = 0.f;

    for (int k0 = 0; k0 < K; k0 += BK) {
        #pragma unroll
        for (int r = 0; r < 2; r++) {
            int row = aRow + r * 64;
            int grow = blockRow + row;
            float4 v = make_float4(0.f, 0.f, 0.f, 0.f);
            if (grow < M) v = *(const float4*)&A[(size_t)grow * K + k0 + aCol];
            As[aCol + 0][row] = v.x;
            As[aCol + 1][row] = v.y;
            As[aCol + 2][row] = v.z;
            As[aCol + 3][row] = v.w;
        }
        #pragma unroll
        for (int r = 0; r < 2; r++) {
            int row = bRow + r * 8;
            *(float4*)&Bs[row][bCol] =
                *(const float4*)&B[(size_t)(k0 + row) * N + bCol];
        }
        __syncthreads();
        #pragma unroll
        for (int kk = 0; kk < BK; kk++) {
            float rM[TM], rN[TN];
            #pragma unroll
            for (int i = 0; i < TM; i++) rM[i] = As[kk][ty * TM + i];
            #pragma unroll
            for (int j = 0; j < TN; j++) rN[j] = Bs[kk][tx * TN + j];
            #pragma unroll
            for (int i = 0; i < TM; i++)
                #pragma unroll
                for (int j = 0; j < TN; j++)
                    acc[i][j] += rM[i] * rN[j];
        }
        __syncthreads();
    }

    #pragma unroll
    for (int i = 0; i < TM; i++) {
        int grow = blockRow + ty * TM + i;
        if (grow >= M) continue;
        #pragma unroll
        for (int j = 0; j < TN; j += 4) {
            int col = tx * TN + j;
            float4 v = make_float4(acc[i][j], acc[i][j + 1],
                                   acc[i][j + 2], acc[i][j + 3]);
            if (bias) {
                v.x += bias[col + 0];
                v.y += bias[col + 1];
                v.z += bias[col + 2];
                v.w += bias[col + 3];
            }
            *(float4*)&C[(size_t)grow * N + col] = v;
        }
    }
}

// ---------------- kernel 2: per-node el/er (warp per node) -----------------
__global__ void elr_kernel(const float* __restrict__ attn_l,
                           const float* __restrict__ attn_r) {
    int warp = (blockIdx.x * blockDim.x + threadIdx.x) >> 5;
    int lane = threadIdx.x & 31;
    if (warp >= V_N) return;
    float4 f  = *(const float4*)&g_ft[(size_t)warp * NHF + lane * 4];
    float4 al = *(const float4*)&attn_l[lane * 4];
    float4 ar = *(const float4*)&attn_r[lane * 4];
    float pl = f.x * al.x + f.y * al.y + f.z * al.z + f.w * al.w;
    float pr = f.x * ar.x + f.y * ar.y + f.z * ar.z + f.w * ar.w;
    // reduce within groups of 8 lanes (one head per group)
    #pragma unroll
    for (int off = 4; off; off >>= 1) {
        pl += __shfl_down_sync(0xffffffffu, pl, off);
        pr += __shfl_down_sync(0xffffffffu, pr, off);
    }
    if ((lane & 7) == 0) {
        g_el[warp * HEADS + (lane >> 3)] = pl;
        g_er[warp * HEADS + (lane >> 3)] = pr;
    }
}

// ---------------- kernel 3: edge logits -> exp, accumulate denominators ----
__global__ void edge_logits_kernel(const float* __restrict__ edge_feats,
                                   const int* __restrict__ src,
                                   const int* __restrict__ dst) {
    __shared__ float sMe[EDGE_IN * HEADS];
    if (threadIdx.x < EDGE_IN * HEADS) sMe[threadIdx.x] = g_Me[threadIdx.x];
    __syncthreads();

    int e = blockIdx.x * blockDim.x + threadIdx.x;
    if (e >= E_N) return;

    float ef[EDGE_IN];
    #pragma unroll
    for (int q = 0; q < 4; q++)
        *(float4*)&ef[q * 4] =
            *(const float4*)&edge_feats[(size_t)e * EDGE_IN + q * 4];

    int s = src[e], d = dst[e];
    float4 elv = *(const float4*)&g_el[s * HEADS];
    float4 erv = *(const float4*)&g_er[d * HEADS];
    float base[4] = {elv.x + erv.x, elv.y + erv.y, elv.z + erv.z, elv.w + erv.w};

    float exv[4];
    #pragma unroll
    for (int h = 0; h < HEADS; h++) {
        float ee = 0.f;
        #pragma unroll
        for (int i = 0; i < EDGE_IN; i++) ee += ef[i] * sMe[i * HEADS + h];
        float x = base[h] + ee;
        x = (x >= 0.f) ? x : 0.2f * x;      // leaky relu
        exv[h] = __expf(x);                 // unstable softmax: |x| <~ 3, safe
    }
    *(float4*)&g_ex[(size_t)e * HEADS] =
        make_float4(exv[0], exv[1], exv[2], exv[3]);
    #pragma unroll
    for (int h = 0; h < HEADS; h++)
        atomicAdd(&g_esum[d * HEADS + h], exv[h]);
}

// ---------------- kernel 4: message passing (warp per edge, vector RED) ----
__global__ void __launch_bounds__(256)
message_kernel(const int* __restrict__ src, const int* __restrict__ dst,
               float* __restrict__ out) {
    int e = (blockIdx.x * blockDim.x + threadIdx.x) >> 5;
    if (e >= E_N) return;
    int lane = threadIdx.x & 31;
    int s = src[e], d = dst[e];

    float a_part = 0.f;
    if (lane < HEADS)
        a_part = g_ex[(size_t)e * HEADS + lane] / g_esum[d * HEADS + lane];
    float a = __shfl_sync(0xffffffffu, a_part, lane >> 3);   // head = lane/8

    float4 f = *(const float4*)&g_ft[(size_t)s * NHF + lane * 4];
    float* addr = &out[(size_t)d * NHF + lane * 4];
    asm volatile("red.global.add.v4.f32 [%0], {%1,%2,%3,%4};"
                 :: "l"(addr), "f"(f.x * a), "f"(f.y * a),
                    "f"(f.z * a), "f"(f.w * a)
                 : "memory");
}

// ---------------- launch ---------------------------------------------------
extern "C" void kernel_launch(void* const* d_in, const int* in_sizes, int n_in,
                              void* d_out, int out_size) {
    const float* node_feats = (const float*)d_in[0];
    const float* edge_feats = (const float*)d_in[1];
    const int*   src        = (const int*)d_in[2];
    const int*   dst        = (const int*)d_in[3];
    const float* W_node     = (const float*)d_in[4];
    const float* W_edge     = (const float*)d_in[5];
    const float* attn_l     = (const float*)d_in[6];
    const float* attn_r     = (const float*)d_in[7];
    // attn_e = d_in[8]
    const float* attn_e     = (const float*)d_in[8];
    const float* res_W      = (const float*)d_in[9];
    const float* bias       = (const float*)d_in[10];
    float* out = (float*)d_out;

    // 0: fold edge attention matrix + zero denominators
    init_kernel<<<200, 256>>>(W_edge, attn_e);
    // 1: ft = X @ W_node  (into g_ft)
    sgemm128<<<(V_N + BM - 1) / BM, 256>>>(node_feats, W_node, V_N,
                                           nullptr, 1, out);
    // 2: out = X @ res_W + bias  (residual initializes the accumulator)
    sgemm128<<<(V_N + BM - 1) / BM, 256>>>(node_feats, res_W, V_N,
                                           bias, 0, out);
    // 3: per-node attention logits el/er
    elr_kernel<<<(V_N * 32) / 256, 256>>>(attn_l, attn_r);
    // 4: edge logits -> exp, denominators
    edge_logits_kernel<<<(E_N + 255) / 256, 256>>>(edge_feats, src, dst);
    // 5: weighted message scatter into out
    message_kernel<<<(E_N * 32) / 256, 256>>>(src, dst, out);
}

// round 2
// speedup vs baseline: 1.0760x; 1.0760x over previous
#include <cuda_runtime.h>
#include <cuda_bf16.h>

#define V_N 50000
#define E_N 800000
#define HEADS 4
#define FOUT 32
#define NHF 128
#define NODE_IN 128
#define EDGE_IN 16

// ---------------- scratch ---------------------------------------------------
__device__ float g_ft[(size_t)V_N * NHF];     // projected node feats  [V,128]
__device__ float g_el[V_N * HEADS];           // left logits  [V,4]
__device__ float g_er[V_N * HEADS];           // right logits [V,4]
__device__ float g_ex[(size_t)E_N * HEADS];   // exp(logit)   [E,4]
__device__ float g_Me[EDGE_IN * HEADS];       // folded edge->logit mat [16,4]
__device__ int   g_count[V_N];                // in-degree counts
__device__ int   g_rank[E_N];                 // rank of edge within its dst
__device__ int   g_off[V_N + 1];              // CSR offsets
__device__ int   g_eid[E_N];                  // CSR edge ids

// ---------------- kernel 0: fold W_edge*attn_e, zero counts ----------------
__global__ void init_kernel(const float* __restrict__ W_edge,
                            const float* __restrict__ attn_e) {
    int tid = blockIdx.x * blockDim.x + threadIdx.x;
    for (int i = tid; i < V_N; i += gridDim.x * blockDim.x)
        g_count[i] = 0;
    if (blockIdx.x == 0 && threadIdx.x < EDGE_IN * HEADS) {
        int i = threadIdx.x / HEADS;
        int h = threadIdx.x % HEADS;
        float s = 0.f;
        #pragma unroll
        for (int f = 0; f < FOUT; f++)
            s += W_edge[i * NHF + h * FOUT + f] * attn_e[h * FOUT + f];
        g_Me[threadIdx.x] = s;
    }
}

// ---------------- kernel 1: SGEMM + optional fused el/er epilogue ----------
#define BM 128
#define BN 128
#define BK 16
#define TM 8
#define TN 8

__global__ void __launch_bounds__(256)
sgemm128(const float* __restrict__ A, const float* __restrict__ B,
         int M, const float* __restrict__ bias,
         const float* __restrict__ attn_l, const float* __restrict__ attn_r,
         int write_ft, float* __restrict__ outC) {
    const int K = 128, N = 128;
    __shared__ float As[BK][BM];
    __shared__ float Bs[BK][BN];
    __shared__ float sEl[BM][HEADS];
    __shared__ float sEr[BM][HEADS];
    float* C = write_ft ? g_ft : outC;

    int tid = threadIdx.x;
    int blockRow = blockIdx.x * BM;
    int tx = tid % 16, ty = tid / 16;

    int aRow = tid / 4;
    int aCol = (tid % 4) * 4;
    int bRow = tid / 32;
    int bCol = (tid % 32) * 4;

    if (attn_l) {
        #pragma unroll
        for (int i = tid; i < BM * HEADS; i += 256) {
            ((float*)sEl)[i] = 0.f;
            ((float*)sEr)[i] = 0.f;
        }
    }

    float acc[TM][TN];
    #pragma unroll
    for (int i = 0; i < TM; i++)
        #pragma unroll
        for (int j = 0; j < TN; j++) acc[i][j] = 0.f;

    for (int k0 = 0; k0 < K; k0 += BK) {
        #pragma unroll
        for (int r = 0; r < 2; r++) {
            int row = aRow + r * 64;
            int grow = blockRow + row;
            float4 v = make_float4(0.f, 0.f, 0.f, 0.f);
            if (grow < M) v = *(const float4*)&A[(size_t)grow * K + k0 + aCol];
            As[aCol + 0][row] = v.x;
            As[aCol + 1][row] = v.y;
            As[aCol + 2][row] = v.z;
            As[aCol + 3][row] = v.w;
        }
        #pragma unroll
        for (int r = 0; r < 2; r++) {
            int row = bRow + r * 8;
            *(float4*)&Bs[row][bCol] =
                *(const float4*)&B[(size_t)(k0 + row) * N + bCol];
        }
        __syncthreads();
        #pragma unroll
        for (int kk = 0; kk < BK; kk++) {
            float rM[TM], rN[TN];
            #pragma unroll
            for (int i = 0; i < TM; i++) rM[i] = As[kk][ty * TM + i];
            #pragma unroll
            for (int j = 0; j < TN; j++) rN[j] = Bs[kk][tx * TN + j];
            #pragma unroll
            for (int i = 0; i < TM; i++)
                #pragma unroll
                for (int j = 0; j < TN; j++)
                    acc[i][j] += rM[i] * rN[j];
        }
        __syncthreads();
    }

    // C store
    #pragma unroll
    for (int i = 0; i < TM; i++) {
        int grow = blockRow + ty * TM + i;
        if (grow >= M) continue;
        #pragma unroll
        for (int j = 0; j < TN; j += 4) {
            int col = tx * TN + j;
            float4 v = make_float4(acc[i][j], acc[i][j + 1],
                                   acc[i][j + 2], acc[i][j + 3]);
            if (bias) {
                v.x += bias[col + 0];
                v.y += bias[col + 1];
                v.z += bias[col + 2];
                v.w += bias[col + 3];
            }
            *(float4*)&C[(size_t)grow * N + col] = v;
        }
    }

    // fused el/er epilogue: el[row,h] = sum_col ft[row,col]*attn_l[col]
    if (attn_l) {
        int h = tx / 4;           // this thread's 8 cols live in head tx/4
        float alv[TN], arv[TN];
        #pragma unroll
        for (int j = 0; j < TN; j++) {
            alv[j] = attn_l[tx * TN + j];
            arv[j] = attn_r[tx * TN + j];
        }
        #pragma unroll
        for (int i = 0; i < TM; i++) {
            float pl = 0.f, pr = 0.f;
            #pragma unroll
            for (int j = 0; j < TN; j++) {
                pl += acc[i][j] * alv[j];
                pr += acc[i][j] * arv[j];
            }
            atomicAdd(&sEl[ty * TM + i][h], pl);
            atomicAdd(&sEr[ty * TM + i][h], pr);
        }
        __syncthreads();
        for (int i = tid; i < BM * HEADS; i += 256) {
            int row = i / HEADS;
            int grow = blockRow + row;
            if (grow < M) {
                g_el[grow * HEADS + (i % HEADS)] = ((float*)sEl)[i];
                g_er[grow * HEADS + (i % HEADS)] = ((float*)sEr)[i];
            }
        }
    }
}

// ---------------- kernel 2: edge logits -> exp, counting-sort rank ---------
__global__ void edge_logits_kernel(const float* __restrict__ edge_feats,
                                   const int* __restrict__ src,
                                   const int* __restrict__ dst) {
    __shared__ float sMe[EDGE_IN * HEADS];
    if (threadIdx.x < EDGE_IN * HEADS) sMe[threadIdx.x] = g_Me[threadIdx.x];
    __syncthreads();

    int e = blockIdx.x * blockDim.x + threadIdx.x;
    if (e >= E_N) return;

    float ef[EDGE_IN];
    #pragma unroll
    for (int q = 0; q < 4; q++)
        *(float4*)&ef[q * 4] =
            *(const float4*)&edge_feats[(size_t)e * EDGE_IN + q * 4];

    int s = src[e], d = dst[e];
    g_rank[e] = atomicAdd(&g_count[d], 1);

    float4 elv = *(const float4*)&g_el[s * HEADS];
    float4 erv = *(const float4*)&g_er[d * HEADS];
    float base[4] = {elv.x + erv.x, elv.y + erv.y, elv.z + erv.z, elv.w + erv.w};

    float exv[4];
    #pragma unroll
    for (int h = 0; h < HEADS; h++) {
        float ee = 0.f;
        #pragma unroll
        for (int i = 0; i < EDGE_IN; i++) ee += ef[i] * sMe[i * HEADS + h];
        float x = base[h] + ee;
        x = (x >= 0.f) ? x : 0.2f * x;
        exv[h] = __expf(x);       // logits bounded (|x|<~4): unstable softmax ok
    }
    *(float4*)&g_ex[(size_t)e * HEADS] =
        make_float4(exv[0], exv[1], exv[2], exv[3]);
}

// ---------------- kernel 3: prefix scan of counts (1 block) ----------------
#define SCAN_T 1024
#define SCAN_CH ((V_N + SCAN_T - 1) / SCAN_T)   // 49

__global__ void __launch_bounds__(SCAN_T)
scan_kernel() {
    __shared__ int sPart[SCAN_T];
    int t = threadIdx.x;
    int base = t * SCAN_CH;
    int sum = 0;
    for (int i = 0; i < SCAN_CH; i++) {
        int idx = base + i;
        if (idx < V_N) sum += g_count[idx];
    }
    sPart[t] = sum;
    __syncthreads();
    for (int off = 1; off < SCAN_T; off <<= 1) {
        int v = (t >= off) ? sPart[t - off] : 0;
        __syncthreads();
        sPart[t] += v;
        __syncthreads();
    }
    int run = (t > 0) ? sPart[t - 1] : 0;
    for (int i = 0; i < SCAN_CH; i++) {
        int idx = base + i;
        if (idx <= V_N) g_off[idx] = run;
        if (idx < V_N) run += g_count[idx];
    }
}

// ---------------- kernel 4: place edges into CSR ---------------------------
__global__ void place_kernel(const int* __restrict__ dst) {
    int e = blockIdx.x * blockDim.x + threadIdx.x;
    if (e >= E_N) return;
    g_eid[g_off[dst[e]] + g_rank[e]] = e;
}

// ---------------- kernel 5: gather per dst node (warp/node) ----------------
__global__ void __launch_bounds__(256)
gather_kernel(const int* __restrict__ src, float* __restrict__ out) {
    int node = (blockIdx.x * blockDim.x + threadIdx.x) >> 5;
    if (node >= V_N) return;
    int lane = threadIdx.x & 31;
    int head = lane >> 3;

    int beg = g_off[node];
    int end = g_off[node + 1];

    float4 acc = make_float4(0.f, 0.f, 0.f, 0.f);
    float s_ex = 0.f;
    const float4* ft4 = (const float4*)g_ft;

    for (int i = beg; i < end; i++) {
        int eid = __ldg(&g_eid[i]);
        int s   = __ldg(&src[eid]);                 // broadcast
        float ax = __ldg(&g_ex[(size_t)eid * HEADS + head]);
        float4 f = ft4[(size_t)s * 32 + lane];
        acc.x += ax * f.x;
        acc.y += ax * f.y;
        acc.z += ax * f.z;
        acc.w += ax * f.w;
        s_ex += ax;
    }
    float inv = (s_ex > 0.f) ? (1.f / s_ex) : 0.f;
    float4* o4 = (float4*)out;
    float4 o = o4[(size_t)node * 32 + lane];        // residual + bias
    o.x += acc.x * inv;
    o.y += acc.y * inv;
    o.z += acc.z * inv;
    o.w += acc.w * inv;
    o4[(size_t)node * 32 + lane] = o;
}

// ---------------- launch ---------------------------------------------------
extern "C" void kernel_launch(void* const* d_in, const int* in_sizes, int n_in,
                              void* d_out, int out_size) {
    const float* node_feats = (const float*)d_in[0];
    const float* edge_feats = (const float*)d_in[1];
    const int*   src        = (const int*)d_in[2];
    const int*   dst        = (const int*)d_in[3];
    const float* W_node     = (const float*)d_in[4];
    const float* W_edge     = (const float*)d_in[5];
    const float* attn_l     = (const float*)d_in[6];
    const float* attn_r     = (const float*)d_in[7];
    const float* attn_e     = (const float*)d_in[8];
    const float* res_W      = (const float*)d_in[9];
    const float* bias       = (const float*)d_in[10];
    float* out = (float*)d_out;

    init_kernel<<<200, 256>>>(W_edge, attn_e);
    // ft = X @ W_node, fused el/er epilogue
    sgemm128<<<(V_N + BM - 1) / BM, 256>>>(node_feats, W_node, V_N,
                                           nullptr, attn_l, attn_r, 1, out);
    // out = X @ res_W + bias
    sgemm128<<<(V_N + BM - 1) / BM, 256>>>(node_feats, res_W, V_N,
                                           bias, nullptr, nullptr, 0, out);
    // per-edge exp(logit) + in-degree counting
    edge_logits_kernel<<<(E_N + 255) / 256, 256>>>(edge_feats, src, dst);
    // CSR build
    scan_kernel<<<1, SCAN_T>>>();
    place_kernel<<<(E_N + 255) / 256, 256>>>(dst);
    // gather + normalize + residual add
    gather_kernel<<<(V_N * 32 + 255) / 256, 256>>>(src, out);
}

// round 4
// speedup vs baseline: 1.2620x; 1.1728x over previous
#include <cuda_runtime.h>
#include <cuda_bf16.h>
#include <cstdint>

#define V_N 50000
#define E_N 800000
#define HEADS 4
#define FOUT 32
#define NHF 128
#define EDGE_IN 16
#define MT ((V_N + 127) / 128)   // 391 M-tiles

// ---------------- scratch ---------------------------------------------------
__device__ float g_ft[(size_t)V_N * NHF];
__device__ float g_el[V_N * HEADS];
__device__ float g_er[V_N * HEADS];
__device__ float g_ex[(size_t)E_N * HEADS];
__device__ float g_Me[EDGE_IN * HEADS];
__device__ int   g_count[V_N];
__device__ int   g_rank[E_N];
__device__ int   g_off[V_N + 1];
__device__ int   g_eid[E_N];
// B = [W_node | res_W] transposed to [n=256][k=128] bf16 hi/lo
__device__ __align__(16) __nv_bfloat16 g_Bhi[256 * 128];
__device__ __align__(16) __nv_bfloat16 g_Blo[256 * 128];

// ---------------- helpers ---------------------------------------------------
static __device__ __forceinline__ uint32_t smem_u32(const void* p) {
    uint32_t a;
    asm("{ .reg .u64 t; cvta.to.shared.u64 t, %1; cvt.u32.u64 %0, t; }"
        : "=r"(a) : "l"(p));
    return a;
}
static __device__ __forceinline__ void ldm4(uint32_t& r0, uint32_t& r1,
                                            uint32_t& r2, uint32_t& r3,
                                            uint32_t addr) {
    asm volatile("ldmatrix.sync.aligned.m8n8.x4.shared.b16 {%0,%1,%2,%3}, [%4];"
                 : "=r"(r0), "=r"(r1), "=r"(r2), "=r"(r3) : "r"(addr));
}
static __device__ __forceinline__ void mma16816(float* c, const uint32_t* a,
                                                const uint32_t* b) {
    asm volatile(
        "mma.sync.aligned.m16n8k16.row.col.f32.bf16.bf16.f32 "
        "{%0,%1,%2,%3}, {%4,%5,%6,%7}, {%8,%9}, {%0,%1,%2,%3};"
        : "+f"(c[0]), "+f"(c[1]), "+f"(c[2]), "+f"(c[3])
        : "r"(a[0]), "r"(a[1]), "r"(a[2]), "r"(a[3]), "r"(b[0]), "r"(b[1]));
}

// ---------------- kernel 0: fold attn_e, zero counts, convert/transpose B --
__global__ void init_kernel(const float* __restrict__ W_edge,
                            const float* __restrict__ attn_e,
                            const float* __restrict__ W_node,
                            const float* __restrict__ res_W) {
    int tid = blockIdx.x * blockDim.x + threadIdx.x;
    int stride = gridDim.x * blockDim.x;
    for (int i = tid; i < V_N; i += stride)
        g_count[i] = 0;
    for (int i = tid; i < 256 * 128; i += stride) {
        int n = i >> 7;      // output column 0..255
        int k = i & 127;
        float w = (n < 128) ? W_node[k * NHF + n] : res_W[k * NHF + (n - 128)];
        __nv_bfloat16 hi = __float2bfloat16(w);
        __nv_bfloat16 lo = __float2bfloat16(w - __bfloat162float(hi));
        g_Bhi[n * 128 + k] = hi;     // n-major [n][k] for .col ldmatrix
        g_Blo[n * 128 + k] = lo;
    }
    if (blockIdx.x == 0 && threadIdx.x < EDGE_IN * HEADS) {
        int i = threadIdx.x / HEADS;
        int h = threadIdx.x % HEADS;
        float s = 0.f;
        #pragma unroll
        for (int f = 0; f < FOUT; f++)
            s += W_edge[i * NHF + h * FOUT + f] * attn_e[h * FOUT + f];
        g_Me[threadIdx.x] = s;
    }
}

// ---------------- kernel 1: mma.sync bf16x3 GEMM, fused epilogues ----------
// SMEM: padded stride 136 bf16 (272 B) rows, conflict-free ldmatrix
#define LDA 136
#define OFF_AHI 0
#define OFF_ALO (128 * LDA * 2)          // 34816
#define OFF_BHI (2 * 128 * LDA * 2)      // 69632
#define OFF_BLO (3 * 128 * LDA * 2)      // 104448
#define SMEM_TOT (4 * 128 * LDA * 2)     // 139264

__global__ void __launch_bounds__(256)
gemm_mma(const float* __restrict__ A,
         const float* __restrict__ attn_l, const float* __restrict__ attn_r,
         const float* __restrict__ bias, float* __restrict__ out) {
    extern __shared__ char smem[];
    uint32_t sb = smem_u32(smem);
    __shared__ float sEl[128 * HEADS];
    __shared__ float sEr[128 * HEADS];

    int tid = threadIdx.x;
    int wid = tid >> 5, lane = tid & 31;
    int warp_m = wid & 1;      // 2 warps along M (64 rows each)
    int warp_n = wid >> 1;     // 4 warps along N (32 cols each)
    int m0 = blockIdx.x * 128;
    int nhalf = blockIdx.y;    // 0: ft+el/er, 1: residual+bias -> out

    if (nhalf == 0)
        for (int i = tid; i < 128 * HEADS; i += 256) {
            sEl[i] = 0.f;
            sEr[i] = 0.f;
        }

    // ---- load + split A tile [128 x 128] ----
    for (int i = tid; i < 4096; i += 256) {
        int row = i >> 5;
        int c4 = (i & 31) << 2;
        float4 v = make_float4(0.f, 0.f, 0.f, 0.f);
        if (m0 + row < V_N)
            v = *(const float4*)&A[(size_t)(m0 + row) * 128 + c4];
        __nv_bfloat16 h0 = __float2bfloat16(v.x), h1 = __float2bfloat16(v.y);
        __nv_bfloat16 h2 = __float2bfloat16(v.z), h3 = __float2bfloat16(v.w);
        __nv_bfloat16 l0 = __float2bfloat16(v.x - __bfloat162float(h0));
        __nv_bfloat16 l1 = __float2bfloat16(v.y - __bfloat162float(h1));
        __nv_bfloat16 l2 = __float2bfloat16(v.z - __bfloat162float(h2));
        __nv_bfloat16 l3 = __float2bfloat16(v.w - __bfloat162float(h3));
        uint32_t off = row * (LDA * 2) + c4 * 2;
        uint2 ph = make_uint2(
            (uint32_t)__bfloat16_as_ushort(h0) | ((uint32_t)__bfloat16_as_ushort(h1) << 16),
            (uint32_t)__bfloat16_as_ushort(h2) | ((uint32_t)__bfloat16_as_ushort(h3) << 16));
        uint2 pl = make_uint2(
            (uint32_t)__bfloat16_as_ushort(l0) | ((uint32_t)__bfloat16_as_ushort(l1) << 16),
            (uint32_t)__bfloat16_as_ushort(l2) | ((uint32_t)__bfloat16_as_ushort(l3) << 16));
        *(uint2*)(smem + OFF_AHI + off) = ph;
        *(uint2*)(smem + OFF_ALO + off) = pl;
    }
    // ---- copy B half [128 n x 128 k], pre-converted ----
    {
        const uint4* bh = (const uint4*)(g_Bhi + nhalf * 128 * 128);
        const uint4* bl = (const uint4*)(g_Blo + nhalf * 128 * 128);
        for (int i = tid; i < 2048; i += 256) {     // 2048 uint4 = 16 KB
            int n = i >> 4;
            int k8 = i & 15;                        // 8 bf16 per uint4
            uint32_t off = n * (LDA * 2) + k8 * 16;
            *(uint4*)(smem + OFF_BHI + off) = bh[i];
            *(uint4*)(smem + OFF_BLO + off) = bl[i];
        }
    }
    __syncthreads();

    // ---- mainloop ----
    float acc[4][4][4];
    #pragma unroll
    for (int i = 0; i < 4; i++)
        #pragma unroll
        for (int j = 0; j < 4; j++)
            #pragma unroll
            for (int t = 0; t < 4; t++) acc[i][j][t] = 0.f;

    // per-thread ldmatrix address bases
    int lrow = lane & 15, lkh = lane >> 4;                 // A mapping
    uint32_t aoff = (warp_m * 64 + lrow) * (LDA * 2) + lkh * 16;
    int r8 = lane & 7, jq = lane >> 4, kh = (lane >> 3) & 1;  // B mapping
    uint32_t boff = (warp_n * 32 + jq * 8 + r8) * (LDA * 2) + kh * 16;

    #pragma unroll
    for (int ks = 0; ks < 8; ks++) {
        uint32_t ahi[4][4], alo[4][4], bhi[4][2], blo[4][2];
        #pragma unroll
        for (int i = 0; i < 4; i++) {
            uint32_t ao = aoff + i * 16 * (LDA * 2) + ks * 32;
            ldm4(ahi[i][0], ahi[i][1], ahi[i][2], ahi[i][3], sb + OFF_AHI + ao);
            ldm4(alo[i][0], alo[i][1], alo[i][2], alo[i][3], sb + OFF_ALO + ao);
        }
        #pragma unroll
        for (int jp = 0; jp < 2; jp++) {
            uint32_t bo = boff + jp * 16 * (LDA * 2) + ks * 32;
            ldm4(bhi[jp * 2][0], bhi[jp * 2][1], bhi[jp * 2 + 1][0],
                 bhi[jp * 2 + 1][1], sb + OFF_BHI + bo);
            ldm4(blo[jp * 2][0], blo[jp * 2][1], blo[jp * 2 + 1][0],
                 blo[jp * 2 + 1][1], sb + OFF_BLO + bo);
        }
        #pragma unroll
        for (int i = 0; i < 4; i++)
            #pragma unroll
            for (int j = 0; j < 4; j++) {
                mma16816(acc[i][j], ahi[i], bhi[j]);
                mma16816(acc[i][j], ahi[i], blo[j]);
                mma16816(acc[i][j], alo[i], bhi[j]);
            }
    }

    // ---- epilogue ----
    if (nhalf == 0) {
        float al[4][2], ar[4][2];
        #pragma unroll
        for (int j = 0; j < 4; j++) {
            int c = warp_n * 32 + j * 8 + (lane & 3) * 2;
            al[j][0] = attn_l[c];     al[j][1] = attn_l[c + 1];
            ar[j][0] = attn_r[c];     ar[j][1] = attn_r[c + 1];
        }
        #pragma unroll
        for (int i = 0; i < 4; i++) {
            #pragma unroll
            for (int r = 0; r < 2; r++) {
                int rl = warp_m * 64 + i * 16 + (lane >> 2) + r * 8;
                int grow = m0 + rl;
                float pl = 0.f, pr = 0.f;
                #pragma unroll
                for (int j = 0; j < 4; j++) {
                    float v0 = acc[i][j][r * 2 + 0], v1 = acc[i][j][r * 2 + 1];
                    pl += v0 * al[j][0] + v1 * al[j][1];
                    pr += v0 * ar[j][0] + v1 * ar[j][1];
                    if (grow < V_N) {
                        int c = warp_n * 32 + j * 8 + (lane & 3) * 2;
                        *(float2*)&g_ft[(size_t)grow * NHF + c] =
                            make_float2(v0, v1);
                    }
                }
                atomicAdd(&sEl[rl * HEADS + warp_n], pl);
                atomicAdd(&sEr[rl * HEADS + warp_n], pr);
            }
        }
        __syncthreads();
        for (int idx = tid; idx < 128 * HEADS; idx += 256) {
            int grow = m0 + (idx >> 2);
            if (grow < V_N) {
                g_el[grow * HEADS + (idx & 3)] = sEl[idx];
                g_er[grow * HEADS + (idx & 3)] = sEr[idx];
            }
        }
    } else {
        #pragma unroll
        for (int i = 0; i < 4; i++)
            #pragma unroll
            for (int r = 0; r < 2; r++) {
                int grow = m0 + warp_m * 64 + i * 16 + (lane >> 2) + r * 8;
                if (grow < V_N) {
                    #pragma unroll
                    for (int j = 0; j < 4; j++) {
                        int c = warp_n * 32 + j * 8 + (lane & 3) * 2;
                        *(float2*)&out[(size_t)grow * NHF + c] =
                            make_float2(acc[i][j][r * 2 + 0] + bias[c],
                                        acc[i][j][r * 2 + 1] + bias[c + 1]);
                    }
                }
            }
    }
}

// ---------------- kernel 2: edge logits -> exp, counting-sort rank ---------
__global__ void edge_logits_kernel(const float* __restrict__ edge_feats,
                                   const int* __restrict__ src,
                                   const int* __restrict__ dst) {
    __shared__ float sMe[EDGE_IN * HEADS];
    if (threadIdx.x < EDGE_IN * HEADS) sMe[threadIdx.x] = g_Me[threadIdx.x];
    __syncthreads();

    int e = blockIdx.x * blockDim.x + threadIdx.x;
    if (e >= E_N) return;

    float ef[EDGE_IN];
    #pragma unroll
    for (int q = 0; q < 4; q++)
        *(float4*)&ef[q * 4] =
            *(const float4*)&edge_feats[(size_t)e * EDGE_IN + q * 4];

    int s = src[e], d = dst[e];
    g_rank[e] = atomicAdd(&g_count[d], 1);

    float4 elv = *(const float4*)&g_el[s * HEADS];
    float4 erv = *(const float4*)&g_er[d * HEADS];
    float base[4] = {elv.x + erv.x, elv.y + erv.y, elv.z + erv.z, elv.w + erv.w};

    float exv[4];
    #pragma unroll
    for (int h = 0; h < HEADS; h++) {
        float ee = 0.f;
        #pragma unroll
        for (int i = 0; i < EDGE_IN; i++) ee += ef[i] * sMe[i * HEADS + h];
        float x = base[h] + ee;
        x = (x >= 0.f) ? x : 0.2f * x;
        exv[h] = __expf(x);   // logits bounded (|x| < ~5): unstable softmax safe
    }
    *(float4*)&g_ex[(size_t)e * HEADS] =
        make_float4(exv[0], exv[1], exv[2], exv[3]);
}

// ---------------- kernel 3: prefix scan of counts (1 block) ----------------
#define SCAN_T 1024
#define SCAN_CH ((V_N + SCAN_T - 1) / SCAN_T)

__global__ void __launch_bounds__(SCAN_T)
scan_kernel() {
    __shared__ int sPart[SCAN_T];
    int t = threadIdx.x;
    int base = t * SCAN_CH;
    int sum = 0;
    for (int i = 0; i < SCAN_CH; i++) {
        int idx = base + i;
        if (idx < V_N) sum += g_count[idx];
    }
    sPart[t] = sum;
    __syncthreads();
    for (int off = 1; off < SCAN_T; off <<= 1) {
        int v = (t >= off) ? sPart[t - off] : 0;
        __syncthreads();
        sPart[t] += v;
        __syncthreads();
    }
    int run = (t > 0) ? sPart[t - 1] : 0;
    for (int i = 0; i < SCAN_CH; i++) {
        int idx = base + i;
        if (idx <= V_N) g_off[idx] = run;
        if (idx < V_N) run += g_count[idx];
    }
}

// ---------------- kernel 4: place edges into CSR ---------------------------
__global__ void place_kernel(const int* __restrict__ dst) {
    int e = blockIdx.x * blockDim.x + threadIdx.x;
    if (e >= E_N) return;
    g_eid[g_off[dst[e]] + g_rank[e]] = e;
}

// ---------------- kernel 5: gather per dst node (warp/node) ----------------
__global__ void __launch_bounds__(256)
gather_kernel(const int* __restrict__ src, float* __restrict__ out) {
    int node = (blockIdx.x * blockDim.x + threadIdx.x) >> 5;
    if (node >= V_N) return;
    int lane = threadIdx.x & 31;
    int head = lane >> 3;

    int beg = g_off[node];
    int end = g_off[node + 1];

    float4 acc = make_float4(0.f, 0.f, 0.f, 0.f);
    float s_ex = 0.f;
    const float4* ft4 = (const float4*)g_ft;

    for (int i = beg; i < end; i++) {
        int eid = __ldg(&g_eid[i]);
        int s   = __ldg(&src[eid]);
        float ax = __ldg(&g_ex[(size_t)eid * HEADS + head]);
        float4 f = ft4[(size_t)s * 32 + lane];
        acc.x += ax * f.x;
        acc.y += ax * f.y;
        acc.z += ax * f.z;
        acc.w += ax * f.w;
        s_ex += ax;
    }
    float inv = (s_ex > 0.f) ? (1.f / s_ex) : 0.f;
    float4* o4 = (float4*)out;
    float4 o = o4[(size_t)node * 32 + lane];   // residual + bias
    o.x += acc.x * inv;
    o.y += acc.y * inv;
    o.z += acc.z * inv;
    o.w += acc.w * inv;
    o4[(size_t)node * 32 + lane] = o;
}

// ---------------- launch ---------------------------------------------------
extern "C" void kernel_launch(void* const* d_in, const int* in_sizes, int n_in,
                              void* d_out, int out_size) {
    const float* node_feats = (const float*)d_in[0];
    const float* edge_feats = (const float*)d_in[1];
    const int*   src        = (const int*)d_in[2];
    const int*   dst        = (const int*)d_in[3];
    const float* W_node     = (const float*)d_in[4];
    const float* W_edge     = (const float*)d_in[5];
    const float* attn_l     = (const float*)d_in[6];
    const float* attn_r     = (const float*)d_in[7];
    const float* attn_e     = (const float*)d_in[8];
    const float* res_W      = (const float*)d_in[9];
    const float* bias       = (const float*)d_in[10];
    float* out = (float*)d_out;

    cudaFuncSetAttribute(gemm_mma,
                         cudaFuncAttributeMaxDynamicSharedMemorySize, SMEM_TOT);

    init_kernel<<<200, 256>>>(W_edge, attn_e, W_node, res_W);
    gemm_mma<<<dim3(MT, 2), 256, SMEM_TOT>>>(node_feats, attn_l, attn_r,
                                             bias, out);
    edge_logits_kernel<<<(E_N + 255) / 256, 256>>>(edge_feats, src, dst);
    scan_kernel<<<1, SCAN_T>>>();
    place_kernel<<<(E_N + 255) / 256, 256>>>(dst);
    gather_kernel<<<(V_N * 32 + 255) / 256, 256>>>(src, out);
}

// round 5
// speedup vs baseline: 1.5588x; 1.2352x over previous
#include <cuda_runtime.h>
#include <cuda_bf16.h>
#include <cstdint>

#define V_N 50000
#define E_N 800000
#define HEADS 4
#define FOUT 32
#define NHF 128
#define EDGE_IN 16
#define MT ((V_N + 127) / 128)   // 391 M-tiles

// ---------------- scratch ---------------------------------------------------
__device__ float g_ft[(size_t)V_N * NHF];
__device__ float g_el[V_N * HEADS];
__device__ float g_er[V_N * HEADS];
__device__ float g_ex[(size_t)E_N * HEADS];
__device__ float g_Me[EDGE_IN * HEADS];
__device__ int   g_count[V_N];
__device__ int   g_rank[E_N];
__device__ int   g_off[V_N + 1];
__device__ int   g_eid[E_N];
// B = [W_node | res_W] transposed to [n=256][k=128] bf16 hi/lo
__device__ __align__(16) __nv_bfloat16 g_Bhi[256 * 128];
__device__ __align__(16) __nv_bfloat16 g_Blo[256 * 128];

// multi-block scan scratch
#define SB 512
#define NB ((V_N + SB - 1) / SB)   // 98
__device__ int g_bsum[NB];

// ---------------- helpers ---------------------------------------------------
static __device__ __forceinline__ uint32_t smem_u32(const void* p) {
    uint32_t a;
    asm("{ .reg .u64 t; cvta.to.shared.u64 t, %1; cvt.u32.u64 %0, t; }"
        : "=r"(a) : "l"(p));
    return a;
}
static __device__ __forceinline__ void ldm4(uint32_t& r0, uint32_t& r1,
                                            uint32_t& r2, uint32_t& r3,
                                            uint32_t addr) {
    asm volatile("ldmatrix.sync.aligned.m8n8.x4.shared.b16 {%0,%1,%2,%3}, [%4];"
                 : "=r"(r0), "=r"(r1), "=r"(r2), "=r"(r3) : "r"(addr));
}
static __device__ __forceinline__ void mma16816(float* c, const uint32_t* a,
                                                const uint32_t* b) {
    asm volatile(
        "mma.sync.aligned.m16n8k16.row.col.f32.bf16.bf16.f32 "
        "{%0,%1,%2,%3}, {%4,%5,%6,%7}, {%8,%9}, {%0,%1,%2,%3};"
        : "+f"(c[0]), "+f"(c[1]), "+f"(c[2]), "+f"(c[3])
        : "r"(a[0]), "r"(a[1]), "r"(a[2]), "r"(a[3]), "r"(b[0]), "r"(b[1]));
}

// ---------------- kernel 0: fold attn_e, zero counts, convert/transpose B --
__global__ void init_kernel(const float* __restrict__ W_edge,
                            const float* __restrict__ attn_e,
                            const float* __restrict__ W_node,
                            const float* __restrict__ res_W) {
    int tid = blockIdx.x * blockDim.x + threadIdx.x;
    int stride = gridDim.x * blockDim.x;
    for (int i = tid; i < V_N; i += stride)
        g_count[i] = 0;
    for (int i = tid; i < 256 * 128; i += stride) {
        int n = i >> 7;      // output column 0..255
        int k = i & 127;
        float w = (n < 128) ? W_node[k * NHF + n] : res_W[k * NHF + (n - 128)];
        __nv_bfloat16 hi = __float2bfloat16(w);
        __nv_bfloat16 lo = __float2bfloat16(w - __bfloat162float(hi));
        g_Bhi[n * 128 + k] = hi;     // n-major [n][k] for .col ldmatrix
        g_Blo[n * 128 + k] = lo;
    }
    if (blockIdx.x == 0 && threadIdx.x < EDGE_IN * HEADS) {
        int i = threadIdx.x / HEADS;
        int h = threadIdx.x % HEADS;
        float s = 0.f;
        #pragma unroll
        for (int f = 0; f < FOUT; f++)
            s += W_edge[i * NHF + h * FOUT + f] * attn_e[h * FOUT + f];
        g_Me[threadIdx.x] = s;
    }
}

// ---------------- kernel 1: mma.sync bf16x3 GEMM, fused epilogues ----------
#define LDA 136
#define OFF_AHI 0
#define OFF_ALO (128 * LDA * 2)
#define OFF_BHI (2 * 128 * LDA * 2)
#define OFF_BLO (3 * 128 * LDA * 2)
#define SMEM_TOT (4 * 128 * LDA * 2)

__global__ void __launch_bounds__(256)
gemm_mma(const float* __restrict__ A,
         const float* __restrict__ attn_l, const float* __restrict__ attn_r,
         const float* __restrict__ bias, float* __restrict__ out) {
    extern __shared__ char smem[];
    uint32_t sb = smem_u32(smem);
    __shared__ float sEl[128 * HEADS];
    __shared__ float sEr[128 * HEADS];

    int tid = threadIdx.x;
    int wid = tid >> 5, lane = tid & 31;
    int warp_m = wid & 1;
    int warp_n = wid >> 1;
    int m0 = blockIdx.x * 128;
    int nhalf = blockIdx.y;

    if (nhalf == 0)
        for (int i = tid; i < 128 * HEADS; i += 256) {
            sEl[i] = 0.f;
            sEr[i] = 0.f;
        }

    for (int i = tid; i < 4096; i += 256) {
        int row = i >> 5;
        int c4 = (i & 31) << 2;
        float4 v = make_float4(0.f, 0.f, 0.f, 0.f);
        if (m0 + row < V_N)
            v = *(const float4*)&A[(size_t)(m0 + row) * 128 + c4];
        __nv_bfloat16 h0 = __float2bfloat16(v.x), h1 = __float2bfloat16(v.y);
        __nv_bfloat16 h2 = __float2bfloat16(v.z), h3 = __float2bfloat16(v.w);
        __nv_bfloat16 l0 = __float2bfloat16(v.x - __bfloat162float(h0));
        __nv_bfloat16 l1 = __float2bfloat16(v.y - __bfloat162float(h1));
        __nv_bfloat16 l2 = __float2bfloat16(v.z - __bfloat162float(h2));
        __nv_bfloat16 l3 = __float2bfloat16(v.w - __bfloat162float(h3));
        uint32_t off = row * (LDA * 2) + c4 * 2;
        uint2 ph = make_uint2(
            (uint32_t)__bfloat16_as_ushort(h0) | ((uint32_t)__bfloat16_as_ushort(h1) << 16),
            (uint32_t)__bfloat16_as_ushort(h2) | ((uint32_t)__bfloat16_as_ushort(h3) << 16));
        uint2 pl = make_uint2(
            (uint32_t)__bfloat16_as_ushort(l0) | ((uint32_t)__bfloat16_as_ushort(l1) << 16),
            (uint32_t)__bfloat16_as_ushort(l2) | ((uint32_t)__bfloat16_as_ushort(l3) << 16));
        *(uint2*)(smem + OFF_AHI + off) = ph;
        *(uint2*)(smem + OFF_ALO + off) = pl;
    }
    {
        const uint4* bh = (const uint4*)(g_Bhi + nhalf * 128 * 128);
        const uint4* bl = (const uint4*)(g_Blo + nhalf * 128 * 128);
        for (int i = tid; i < 2048; i += 256) {
            int n = i >> 4;
            int k8 = i & 15;
            uint32_t off = n * (LDA * 2) + k8 * 16;
            *(uint4*)(smem + OFF_BHI + off) = bh[i];
            *(uint4*)(smem + OFF_BLO + off) = bl[i];
        }
    }
    __syncthreads();

    float acc[4][4][4];
    #pragma unroll
    for (int i = 0; i < 4; i++)
        #pragma unroll
        for (int j = 0; j < 4; j++)
            #pragma unroll
            for (int t = 0; t < 4; t++) acc[i][j][t] = 0.f;

    int lrow = lane & 15, lkh = lane >> 4;
    uint32_t aoff = (warp_m * 64 + lrow) * (LDA * 2) + lkh * 16;
    int r8 = lane & 7, jq = lane >> 4, kh = (lane >> 3) & 1;
    uint32_t boff = (warp_n * 32 + jq * 8 + r8) * (LDA * 2) + kh * 16;

    #pragma unroll
    for (int ks = 0; ks < 8; ks++) {
        uint32_t ahi[4][4], alo[4][4], bhi[4][2], blo[4][2];
        #pragma unroll
        for (int i = 0; i < 4; i++) {
            uint32_t ao = aoff + i * 16 * (LDA * 2) + ks * 32;
            ldm4(ahi[i][0], ahi[i][1], ahi[i][2], ahi[i][3], sb + OFF_AHI + ao);
            ldm4(alo[i][0], alo[i][1], alo[i][2], alo[i][3], sb + OFF_ALO + ao);
        }
        #pragma unroll
        for (int jp = 0; jp < 2; jp++) {
            uint32_t bo = boff + jp * 16 * (LDA * 2) + ks * 32;
            ldm4(bhi[jp * 2][0], bhi[jp * 2][1], bhi[jp * 2 + 1][0],
                 bhi[jp * 2 + 1][1], sb + OFF_BHI + bo);
            ldm4(blo[jp * 2][0], blo[jp * 2][1], blo[jp * 2 + 1][0],
                 blo[jp * 2 + 1][1], sb + OFF_BLO + bo);
        }
        #pragma unroll
        for (int i = 0; i < 4; i++)
            #pragma unroll
            for (int j = 0; j < 4; j++) {
                mma16816(acc[i][j], ahi[i], bhi[j]);
                mma16816(acc[i][j], ahi[i], blo[j]);
                mma16816(acc[i][j], alo[i], bhi[j]);
            }
    }

    if (nhalf == 0) {
        float al[4][2], ar[4][2];
        #pragma unroll
        for (int j = 0; j < 4; j++) {
            int c = warp_n * 32 + j * 8 + (lane & 3) * 2;
            al[j][0] = attn_l[c];     al[j][1] = attn_l[c + 1];
            ar[j][0] = attn_r[c];     ar[j][1] = attn_r[c + 1];
        }
        #pragma unroll
        for (int i = 0; i < 4; i++) {
            #pragma unroll
            for (int r = 0; r < 2; r++) {
                int rl = warp_m * 64 + i * 16 + (lane >> 2) + r * 8;
                int grow = m0 + rl;
                float pl = 0.f, pr = 0.f;
                #pragma unroll
                for (int j = 0; j < 4; j++) {
                    float v0 = acc[i][j][r * 2 + 0], v1 = acc[i][j][r * 2 + 1];
                    pl += v0 * al[j][0] + v1 * al[j][1];
                    pr += v0 * ar[j][0] + v1 * ar[j][1];
                    if (grow < V_N) {
                        int c = warp_n * 32 + j * 8 + (lane & 3) * 2;
                        *(float2*)&g_ft[(size_t)grow * NHF + c] =
                            make_float2(v0, v1);
                    }
                }
                atomicAdd(&sEl[rl * HEADS + warp_n], pl);
                atomicAdd(&sEr[rl * HEADS + warp_n], pr);
            }
        }
        __syncthreads();
        for (int idx = tid; idx < 128 * HEADS; idx += 256) {
            int grow = m0 + (idx >> 2);
            if (grow < V_N) {
                g_el[grow * HEADS + (idx & 3)] = sEl[idx];
                g_er[grow * HEADS + (idx & 3)] = sEr[idx];
            }
        }
    } else {
        #pragma unroll
        for (int i = 0; i < 4; i++)
            #pragma unroll
            for (int r = 0; r < 2; r++) {
                int grow = m0 + warp_m * 64 + i * 16 + (lane >> 2) + r * 8;
                if (grow < V_N) {
                    #pragma unroll
                    for (int j = 0; j < 4; j++) {
                        int c = warp_n * 32 + j * 8 + (lane & 3) * 2;
                        *(float2*)&out[(size_t)grow * NHF + c] =
                            make_float2(acc[i][j][r * 2 + 0] + bias[c],
                                        acc[i][j][r * 2 + 1] + bias[c + 1]);
                    }
                }
            }
    }
}

// ---------------- kernel 2: edge logits -> exp, counting-sort rank ---------
__global__ void edge_logits_kernel(const float* __restrict__ edge_feats,
                                   const int* __restrict__ src,
                                   const int* __restrict__ dst) {
    __shared__ float sMe[EDGE_IN * HEADS];
    if (threadIdx.x < EDGE_IN * HEADS) sMe[threadIdx.x] = g_Me[threadIdx.x];
    __syncthreads();

    int e = blockIdx.x * blockDim.x + threadIdx.x;
    if (e >= E_N) return;

    float ef[EDGE_IN];
    #pragma unroll
    for (int q = 0; q < 4; q++)
        *(float4*)&ef[q * 4] =
            *(const float4*)&edge_feats[(size_t)e * EDGE_IN + q * 4];

    int s = src[e], d = dst[e];
    g_rank[e] = atomicAdd(&g_count[d], 1);

    float4 elv = *(const float4*)&g_el[s * HEADS];
    float4 erv = *(const float4*)&g_er[d * HEADS];
    float base[4] = {elv.x + erv.x, elv.y + erv.y, elv.z + erv.z, elv.w + erv.w};

    float exv[4];
    #pragma unroll
    for (int h = 0; h < HEADS; h++) {
        float ee = 0.f;
        #pragma unroll
        for (int i = 0; i < EDGE_IN; i++) ee += ef[i] * sMe[i * HEADS + h];
        float x = base[h] + ee;
        x = (x >= 0.f) ? x : 0.2f * x;
        exv[h] = __expf(x);   // logits bounded (|x| < ~5): unstable softmax safe
    }
    *(float4*)&g_ex[(size_t)e * HEADS] =
        make_float4(exv[0], exv[1], exv[2], exv[3]);
}

// ---------------- multi-block scan (3 tiny kernels) ------------------------
__global__ void __launch_bounds__(SB)
scan1_kernel() {
    __shared__ int s[SB];
    int t = threadIdx.x;
    int idx = blockIdx.x * SB + t;
    int c = (idx < V_N) ? g_count[idx] : 0;
    s[t] = c;
    __syncthreads();
    int val = c;
    #pragma unroll
    for (int off = 1; off < SB; off <<= 1) {
        int v = (t >= off) ? s[t - off] : 0;
        __syncthreads();
        val += v;
        s[t] = val;
        __syncthreads();
    }
    if (idx < V_N) g_off[idx] = val - c;          // exclusive
    if (t == SB - 1) g_bsum[blockIdx.x] = val;    // block total
}

__global__ void __launch_bounds__(128)
scan2_kernel() {
    __shared__ int s[NB];
    int t = threadIdx.x;
    if (t < NB) s[t] = g_bsum[t];
    __syncthreads();
    if (t == 0) {
        int run = 0;
        #pragma unroll
        for (int i = 0; i < NB; i++) {
            int v = s[i];
            s[i] = run;
            run += v;
        }
    }
    __syncthreads();
    if (t < NB) g_bsum[t] = s[t];
}

__global__ void __launch_bounds__(SB)
scan3_kernel() {
    int idx = blockIdx.x * SB + threadIdx.x;
    if (idx < V_N) g_off[idx] += g_bsum[blockIdx.x];
    if (idx == 0) g_off[V_N] = E_N;
}

// ---------------- kernel 4: place edges into CSR ---------------------------
__global__ void place_kernel(const int* __restrict__ dst) {
    int e = blockIdx.x * blockDim.x + threadIdx.x;
    if (e >= E_N) return;
    g_eid[g_off[dst[e]] + g_rank[e]] = e;
}

// ---------------- kernel 5: gather per dst node (warp/node) ----------------
__global__ void __launch_bounds__(256)
gather_kernel(const int* __restrict__ src, float* __restrict__ out) {
    int node = (blockIdx.x * blockDim.x + threadIdx.x) >> 5;
    if (node >= V_N) return;
    int lane = threadIdx.x & 31;
    int head = lane >> 3;

    int beg = g_off[node];
    int end = g_off[node + 1];

    float4 acc = make_float4(0.f, 0.f, 0.f, 0.f);
    float s_ex = 0.f;
    const float4* ft4 = (const float4*)g_ft;

    for (int i = beg; i < end; i++) {
        int eid = __ldg(&g_eid[i]);
        int s   = __ldg(&src[eid]);
        float ax = __ldg(&g_ex[(size_t)eid * HEADS + head]);
        float4 f = ft4[(size_t)s * 32 + lane];
        acc.x += ax * f.x;
        acc.y += ax * f.y;
        acc.z += ax * f.z;
        acc.w += ax * f.w;
        s_ex += ax;
    }
    float inv = (s_ex > 0.f) ? (1.f / s_ex) : 0.f;
    float4* o4 = (float4*)out;
    float4 o = o4[(size_t)node * 32 + lane];
    o.x += acc.x * inv;
    o.y += acc.y * inv;
    o.z += acc.z * inv;
    o.w += acc.w * inv;
    o4[(size_t)node * 32 + lane] = o;
}

// ---------------- launch ---------------------------------------------------
extern "C" void kernel_launch(void* const* d_in, const int* in_sizes, int n_in,
                              void* d_out, int out_size) {
    const float* node_feats = (const float*)d_in[0];
    const float* edge_feats = (const float*)d_in[1];
    const int*   src        = (const int*)d_in[2];
    const int*   dst        = (const int*)d_in[3];
    const float* W_node     = (const float*)d_in[4];
    const float* W_edge     = (const float*)d_in[5];
    const float* attn_l     = (const float*)d_in[6];
    const float* attn_r     = (const float*)d_in[7];
    const float* attn_e     = (const float*)d_in[8];
    const float* res_W      = (const float*)d_in[9];
    const float* bias       = (const float*)d_in[10];
    float* out = (float*)d_out;

    cudaFuncSetAttribute(gemm_mma,
                         cudaFuncAttributeMaxDynamicSharedMemorySize, SMEM_TOT);

    init_kernel<<<200, 256>>>(W_edge, attn_e, W_node, res_W);
    gemm_mma<<<dim3(MT, 2), 256, SMEM_TOT>>>(node_feats, attn_l, attn_r,
                                             bias, out);
    edge_logits_kernel<<<(E_N + 255) / 256, 256>>>(edge_feats, src, dst);
    scan1_kernel<<<NB, SB>>>();
    scan2_kernel<<<1, 128>>>();
    scan3_kernel<<<NB, SB>>>();
    place_kernel<<<(E_N + 255) / 256, 256>>>(dst);
    gather_kernel<<<(V_N * 32 + 255) / 256, 256>>>(src, out);
}